// round 11
// baseline (speedup 1.0000x reference)
#include <cuda_runtime.h>
#include <cstdint>

// Problem constants (shapes fixed by dataset).
constexpr int Hdim   = 128;
constexpr int NLEAF  = 8192;
constexpr int NBATCH = 8;
constexpr int NL     = NBATCH * NLEAF;     // 65536 leaf edges
constexpr int NPT    = 24575;              // nodes per tree
constexpr int NN     = NBATCH * NPT;       // 196600 total nodes
constexpr int DEPTH  = 14;

// float2-unit strides (hi/lo interleaved), even for 16B alignment
constexpr int A2_BIG   = 262;              // K=256 activations + pad
constexpr int A2_SMALL = 134;              // K=128 activations + pad
constexpr int W2STR    = 134;              // weight chunk stride

constexpr int SMEM_MMA_01 = (64 * A2_BIG + 64 * W2STR) * 8;            // 202752
constexpr int SMEM_MMA_2  = (64 * A2_SMALL + 64 * W2STR) * 8 + 256;    // 137728

// scalar small kernel (R4 config)
constexpr int ASTR_BIG   = 260;
constexpr int ASTR_SMALL = 132;
constexpr int SMEM_SMALL = (16 * ASTR_BIG + 64 * Hdim) * 4;            // 49408

// ---------------- tf32 helpers ----------------
#define CVT_TF32(d, s) asm("cvt.rna.tf32.f32 %0, %1;" : "=r"(d) : "f"(s))

__device__ __forceinline__ void split_tf32(float v, uint32_t& hi, uint32_t& lo) {
    CVT_TF32(hi, v);
    float r = v - __uint_as_float(hi);
    CVT_TF32(lo, r);
}

__device__ __forceinline__ float2 split2(float v) {
    uint32_t h, l;
    split_tf32(v, h, l);
    return make_float2(__uint_as_float(h), __uint_as_float(l));
}

__device__ __forceinline__ void mma_tf32(float (&c)[4], const uint32_t (&a)[4],
                                         uint32_t b0, uint32_t b1) {
    asm volatile(
        "mma.sync.aligned.m16n8k8.row.col.f32.tf32.tf32.f32 "
        "{%0,%1,%2,%3}, {%4,%5,%6,%7}, {%8,%9}, {%0,%1,%2,%3};"
        : "+f"(c[0]), "+f"(c[1]), "+f"(c[2]), "+f"(c[3])
        : "r"(a[0]), "r"(a[1]), "r"(a[2]), "r"(a[3]), "r"(b0), "r"(b1));
}

// fragment registers for one k-step (k=8) of a 32x32 warp tile
struct Frag {
    uint32_t ah[2][4], al[2][4];   // A hi/lo, 2 m-tiles
    uint32_t bh[4][2], bl[4][2];   // B hi/lo, 4 n-tiles
};

template<int ASTR2>
__device__ __forceinline__ void load_frag(const float2* __restrict__ sA2,
                                          const float2* __restrict__ sW2,
                                          int k0, int ks, int mrow0, int ncol0,
                                          int qr, int qc, Frag& F)
{
    const int kc   = k0 + ks * 8 + qc;   // absolute k for A
    const int krow = ks * 8 + qc;        // chunk-relative k for W
#pragma unroll
    for (int mt = 0; mt < 2; ++mt) {
        const int rb = mrow0 + 16 * mt;
        float2 a0 = sA2[(rb + qr    ) * ASTR2 + kc    ];
        float2 a1 = sA2[(rb + qr + 8) * ASTR2 + kc    ];
        float2 a2 = sA2[(rb + qr    ) * ASTR2 + kc + 4];
        float2 a3 = sA2[(rb + qr + 8) * ASTR2 + kc + 4];
        F.ah[mt][0] = __float_as_uint(a0.x); F.al[mt][0] = __float_as_uint(a0.y);
        F.ah[mt][1] = __float_as_uint(a1.x); F.al[mt][1] = __float_as_uint(a1.y);
        F.ah[mt][2] = __float_as_uint(a2.x); F.al[mt][2] = __float_as_uint(a2.y);
        F.ah[mt][3] = __float_as_uint(a3.x); F.al[mt][3] = __float_as_uint(a3.y);
    }
#pragma unroll
    for (int nt = 0; nt < 4; ++nt) {
        const int nb = ncol0 + 8 * nt + qr;
        float2 w0 = sW2[(krow    ) * W2STR + nb];
        float2 w1 = sW2[(krow + 4) * W2STR + nb];
        F.bh[nt][0] = __float_as_uint(w0.x); F.bl[nt][0] = __float_as_uint(w0.y);
        F.bh[nt][1] = __float_as_uint(w1.x); F.bl[nt][1] = __float_as_uint(w1.y);
    }
}

__device__ __forceinline__ void mma_frag(const Frag& F,
                                         float (&Cm)[2][4][4], float (&Cc)[2][4][4])
{
    // pass 1: hi*lo into Cc (8 independent)
#pragma unroll
    for (int mt = 0; mt < 2; ++mt)
#pragma unroll
        for (int nt = 0; nt < 4; ++nt)
            mma_tf32(Cc[mt][nt], F.ah[mt], F.bl[nt][0], F.bl[nt][1]);
    // pass 2: lo*hi into Cc
#pragma unroll
    for (int mt = 0; mt < 2; ++mt)
#pragma unroll
        for (int nt = 0; nt < 4; ++nt)
            mma_tf32(Cc[mt][nt], F.al[mt], F.bh[nt][0], F.bh[nt][1]);
    // pass 3: hi*hi into Cm (independent of Cc chains)
#pragma unroll
    for (int mt = 0; mt < 2; ++mt)
#pragma unroll
        for (int nt = 0; nt < 4; ++nt)
            mma_tf32(Cm[mt][nt], F.ah[mt], F.bh[nt][0], F.bh[nt][1]);
}

// one MLP layer via 3xTF32, hi/lo-interleaved operands, double-buffered frags
template<int K, int ASTR2>
__device__ __forceinline__ void layer_mma(const float2* __restrict__ sA2,
                                          float2* __restrict__ sW2,
                                          const float* __restrict__ w,
                                          int tid, int mrow0, int ncol0,
                                          int qr, int qc,
                                          float (&Cm)[2][4][4], float (&Cc)[2][4][4])
{
#pragma unroll 1
    for (int k0 = 0; k0 < K; k0 += 64) {
        // stage + split 64x128 weight chunk (interleaved hi/lo)
        for (int idx = tid; idx < 64 * 32; idx += 256) {
            int kr = idx >> 5, c4 = idx & 31;
            float4 v = reinterpret_cast<const float4*>(w + (size_t)(k0 + kr) * Hdim)[c4];
            float2 s0 = split2(v.x), s1 = split2(v.y), s2 = split2(v.z), s3 = split2(v.w);
            float4* dst = reinterpret_cast<float4*>(sW2 + kr * W2STR + c4 * 4);
            dst[0] = make_float4(s0.x, s0.y, s1.x, s1.y);
            dst[1] = make_float4(s2.x, s2.y, s3.x, s3.y);
        }
        __syncthreads();

        Frag F0, F1;
        load_frag<ASTR2>(sA2, sW2, k0, 0, mrow0, ncol0, qr, qc, F0);
#pragma unroll
        for (int ks2 = 0; ks2 < 4; ++ks2) {
            load_frag<ASTR2>(sA2, sW2, k0, 2 * ks2 + 1, mrow0, ncol0, qr, qc, F1);
            mma_frag(F0, Cm, Cc);
            if (ks2 < 3)
                load_frag<ASTR2>(sA2, sW2, k0, 2 * ks2 + 2, mrow0, ncol0, qr, qc, F0);
            mma_frag(F1, Cm, Cc);
        }
        __syncthreads();
    }
}

__device__ __forceinline__ void zero_C(float (&C)[2][4][4]) {
#pragma unroll
    for (int mt = 0; mt < 2; ++mt)
#pragma unroll
        for (int nt = 0; nt < 4; ++nt)
#pragma unroll
            for (int j = 0; j < 4; ++j) C[mt][nt][j] = 0.f;
}

// merge + bias + relu + split-store interleaved into sA2 (stride A2_SMALL)
__device__ __forceinline__ void epi_relu_split(float (&Cm)[2][4][4], float (&Cc)[2][4][4],
                                               const float* __restrict__ b,
                                               float2* __restrict__ sA2,
                                               int mrow0, int ncol0, int qr, int qc)
{
#pragma unroll
    for (int mt = 0; mt < 2; ++mt) {
        const int rb = mrow0 + 16 * mt + qr;
#pragma unroll
        for (int nt = 0; nt < 4; ++nt) {
            const int nb = ncol0 + 8 * nt + 2 * qc;
            float2 bv = *reinterpret_cast<const float2*>(b + nb);
            float v0 = Cm[mt][nt][0] + Cc[mt][nt][0] + bv.x;
            float v1 = Cm[mt][nt][1] + Cc[mt][nt][1] + bv.y;
            float v2 = Cm[mt][nt][2] + Cc[mt][nt][2] + bv.x;
            float v3 = Cm[mt][nt][3] + Cc[mt][nt][3] + bv.y;
            v0 = v0 > 0.f ? v0 : 0.f;  v1 = v1 > 0.f ? v1 : 0.f;
            v2 = v2 > 0.f ? v2 : 0.f;  v3 = v3 > 0.f ? v3 : 0.f;
            float2 s0 = split2(v0), s1 = split2(v1);
            float2 s2 = split2(v2), s3 = split2(v3);
            *reinterpret_cast<float4*>(sA2 + rb * A2_SMALL + nb) =
                make_float4(s0.x, s0.y, s1.x, s1.y);
            *reinterpret_cast<float4*>(sA2 + (rb + 8) * A2_SMALL + nb) =
                make_float4(s2.x, s2.y, s3.x, s3.y);
        }
    }
}

// MODE 0: nem — in=[x[esrc[e]], ef[e]]               (K=256), out -> x[edst[e]]        (set)
// MODE 1: mg  — in=[x[esrc[s+r]], x[esrc[s+half+r]]] (K=256), out -> x[edst[s+half+r]] (set)
// MODE 2: mr  — in=[x[edst[e]], state[e]]            (K=129), out -> x[esrc[e]] += out
template<int MODE>
__global__ void __launch_bounds__(256, 1)
mlp_mma(float* __restrict__ x,
        const float* __restrict__ ef,
        const int* __restrict__ esrc,
        const int* __restrict__ edst,
        const float* __restrict__ est,
        const float* __restrict__ w0, const float* __restrict__ b0,
        const float* __restrict__ w1, const float* __restrict__ b1,
        const float* __restrict__ w2, const float* __restrict__ b2,
        int s, int half, int nrows)
{
    constexpr int ASTR2_0 = (MODE == 2) ? A2_SMALL : A2_BIG;
    extern __shared__ float2 sm2[];
    float2* sA2 = sm2;
    float2* sW2 = sm2 + 64 * ASTR2_0;
    float*  sState = reinterpret_cast<float*>(sW2 + 64 * W2STR);   // mode 2 only

    const int tid  = threadIdx.x;
    const int wid  = tid >> 5, lane = tid & 31;
    const int qr   = lane >> 2, qc = lane & 3;
    const int mrow0 = (wid >> 2) * 32;
    const int ncol0 = (wid & 3) * 32;
    const int row_base = blockIdx.x * 64;

    // ---- gather, split hi/lo interleaved into sA2 ----
    if (MODE == 0 || MODE == 1) {
        for (int idx = tid; idx < 64 * 64; idx += 256) {
            int r = idx >> 6, c4 = idx & 63;
            int row = row_base + r;
            if (row < nrows) {
                float4 v;
                if (c4 < 32) {
                    int node = esrc[s + row];
                    v = reinterpret_cast<const float4*>(x + (size_t)node * Hdim)[c4];
                } else if (MODE == 0) {
                    v = reinterpret_cast<const float4*>(ef + (size_t)(s + row) * Hdim)[c4 - 32];
                } else {
                    int node = esrc[s + half + row];
                    v = reinterpret_cast<const float4*>(x + (size_t)node * Hdim)[c4 - 32];
                }
                float2 s0 = split2(v.x), s1 = split2(v.y), s2 = split2(v.z), s3 = split2(v.w);
                float4* dst = reinterpret_cast<float4*>(sA2 + r * A2_BIG + c4 * 4);
                dst[0] = make_float4(s0.x, s0.y, s1.x, s1.y);
                dst[1] = make_float4(s2.x, s2.y, s3.x, s3.y);
            }
        }
    } else {
        for (int idx = tid; idx < 64 * 32; idx += 256) {
            int r = idx >> 5, c4 = idx & 31;
            int row = row_base + r;
            if (row < nrows) {
                int node = edst[s + row];
                float4 v = reinterpret_cast<const float4*>(x + (size_t)node * Hdim)[c4];
                float2 s0 = split2(v.x), s1 = split2(v.y), s2 = split2(v.z), s3 = split2(v.w);
                float4* dst = reinterpret_cast<float4*>(sA2 + r * A2_SMALL + c4 * 4);
                dst[0] = make_float4(s0.x, s0.y, s1.x, s1.y);
                dst[1] = make_float4(s2.x, s2.y, s3.x, s3.y);
            }
        }
        for (int r = tid; r < 64; r += 256) {
            int row = row_base + r;
            sState[r] = (row < nrows) ? est[s + row] : 0.f;
        }
    }
    __syncthreads();

    float Cm[2][4][4], Cc[2][4][4];

    // ---- layer 0 ----
    zero_C(Cm); zero_C(Cc);
    if (MODE == 2) {
        layer_mma<128, A2_SMALL>(sA2, sW2, w0, tid, mrow0, ncol0, qr, qc, Cm, Cc);
        // state column (row 128 of w0), exact fp32
#pragma unroll
        for (int mt = 0; mt < 2; ++mt) {
            float st0 = sState[mrow0 + 16 * mt + qr];
            float st1 = sState[mrow0 + 16 * mt + qr + 8];
#pragma unroll
            for (int nt = 0; nt < 4; ++nt) {
                int nb = ncol0 + 8 * nt + 2 * qc;
                float2 wsv = *reinterpret_cast<const float2*>(w0 + (size_t)128 * Hdim + nb);
                Cm[mt][nt][0] = fmaf(st0, wsv.x, Cm[mt][nt][0]);
                Cm[mt][nt][1] = fmaf(st0, wsv.y, Cm[mt][nt][1]);
                Cm[mt][nt][2] = fmaf(st1, wsv.x, Cm[mt][nt][2]);
                Cm[mt][nt][3] = fmaf(st1, wsv.y, Cm[mt][nt][3]);
            }
        }
    } else {
        layer_mma<256, A2_BIG>(sA2, sW2, w0, tid, mrow0, ncol0, qr, qc, Cm, Cc);
    }
    epi_relu_split(Cm, Cc, b0, sA2, mrow0, ncol0, qr, qc);
    __syncthreads();

    // ---- layer 1 ----
    zero_C(Cm); zero_C(Cc);
    layer_mma<128, A2_SMALL>(sA2, sW2, w1, tid, mrow0, ncol0, qr, qc, Cm, Cc);
    epi_relu_split(Cm, Cc, b1, sA2, mrow0, ncol0, qr, qc);
    __syncthreads();

    // ---- layer 2: scatter straight from registers ----
    zero_C(Cm); zero_C(Cc);
    layer_mma<128, A2_SMALL>(sA2, sW2, w2, tid, mrow0, ncol0, qr, qc, Cm, Cc);
#pragma unroll
    for (int mt = 0; mt < 2; ++mt) {
#pragma unroll
        for (int j = 0; j < 2; ++j) {
            int r = mrow0 + 16 * mt + qr + 8 * j;
            int row = row_base + r;
            if (row >= nrows) continue;
            int node;
            if (MODE == 0)      node = edst[s + row];
            else if (MODE == 1) node = edst[s + half + row];
            else                node = esrc[s + row];
            float* p = x + (size_t)node * Hdim;
#pragma unroll
            for (int nt = 0; nt < 4; ++nt) {
                int nb = ncol0 + 8 * nt + 2 * qc;
                float2 bv = *reinterpret_cast<const float2*>(b2 + nb);
                float v0 = Cm[mt][nt][2 * j]     + Cc[mt][nt][2 * j]     + bv.x;
                float v1 = Cm[mt][nt][2 * j + 1] + Cc[mt][nt][2 * j + 1] + bv.y;
                if (MODE == 2) {
                    float2 o = *reinterpret_cast<const float2*>(p + nb);
                    v0 += o.x; v1 += o.y;
                }
                *reinterpret_cast<float2*>(p + nb) = make_float2(v0, v1);
            }
        }
    }
}

// =============== SMALL kernel: 16-row tiles, 256 threads, scalar (R4) ======

template<int K, int ASTR>
__device__ __forceinline__ void layer_acc_s(const float* __restrict__ sA,
                                            float* __restrict__ sW,
                                            const float* __restrict__ w,
                                            int tid, int r0, int c0,
                                            float (&acc)[8])
{
#pragma unroll 1
    for (int k0 = 0; k0 < K; k0 += 64) {
        for (int idx = tid; idx < 64 * 32; idx += 256) {
            reinterpret_cast<float4*>(sW)[idx] =
                reinterpret_cast<const float4*>(w + (size_t)k0 * Hdim)[idx];
        }
        __syncthreads();
#pragma unroll 4
        for (int kq = 0; kq < 16; ++kq) {
            float4 av = *reinterpret_cast<const float4*>(sA + r0 * ASTR + k0 + kq * 4);
#pragma unroll
            for (int t = 0; t < 4; ++t) {
                const float* wr = sW + (kq * 4 + t) * Hdim + c0;
                float4 w0v = *reinterpret_cast<const float4*>(wr);
                float4 w1v = *reinterpret_cast<const float4*>(wr + 4);
                float a = reinterpret_cast<const float*>(&av)[t];
                acc[0] = fmaf(a, w0v.x, acc[0]);
                acc[1] = fmaf(a, w0v.y, acc[1]);
                acc[2] = fmaf(a, w0v.z, acc[2]);
                acc[3] = fmaf(a, w0v.w, acc[3]);
                acc[4] = fmaf(a, w1v.x, acc[4]);
                acc[5] = fmaf(a, w1v.y, acc[5]);
                acc[6] = fmaf(a, w1v.z, acc[6]);
                acc[7] = fmaf(a, w1v.w, acc[7]);
            }
        }
        __syncthreads();
    }
}

template<int MODE>
__global__ void __launch_bounds__(256)
mlp_small(float* __restrict__ x,
          const float* __restrict__ ef,
          const int* __restrict__ esrc,
          const int* __restrict__ edst,
          const float* __restrict__ est,
          const float* __restrict__ w0, const float* __restrict__ b0,
          const float* __restrict__ w1, const float* __restrict__ b1,
          const float* __restrict__ w2, const float* __restrict__ b2,
          int s, int half, int nrows)
{
    extern __shared__ float sm[];
    float* sA = sm;
    float* sW = sm + 16 * ASTR_BIG;

    const int tid = threadIdx.x;
    const int cx = tid & 15, ry = tid >> 4;
    const int c0 = cx * 8, r0 = ry;
    const int row_base = blockIdx.x * 16;

    if (MODE == 0 || MODE == 1) {
        for (int idx = tid; idx < 16 * 64; idx += 256) {
            int r = idx >> 6, c4 = idx & 63;
            int row = row_base + r;
            if (row < nrows) {
                float4 v;
                if (c4 < 32) {
                    int node = esrc[s + row];
                    v = reinterpret_cast<const float4*>(x + (size_t)node * Hdim)[c4];
                } else if (MODE == 0) {
                    v = reinterpret_cast<const float4*>(ef + (size_t)(s + row) * Hdim)[c4 - 32];
                } else {
                    int node = esrc[s + half + row];
                    v = reinterpret_cast<const float4*>(x + (size_t)node * Hdim)[c4 - 32];
                }
                reinterpret_cast<float4*>(sA + r * ASTR_BIG)[c4] = v;
            }
        }
    } else {
        for (int idx = tid; idx < 16 * 32; idx += 256) {
            int r = idx >> 5, c4 = idx & 31;
            int row = row_base + r;
            if (row < nrows) {
                int node = edst[s + row];
                float4 v = reinterpret_cast<const float4*>(x + (size_t)node * Hdim)[c4];
                reinterpret_cast<float4*>(sA + r * ASTR_SMALL)[c4] = v;
            }
        }
        for (int r = tid; r < 16; r += 256) {
            int row = row_base + r;
            sA[r * ASTR_SMALL + 128] = (row < nrows) ? est[s + row] : 0.f;
        }
    }
    __syncthreads();

    float acc[8];

#pragma unroll
    for (int j = 0; j < 8; ++j) acc[j] = 0.f;
    if (MODE == 2) {
        layer_acc_s<128, ASTR_SMALL>(sA, sW, w0, tid, r0, c0, acc);
        const float* wsr = w0 + (size_t)128 * Hdim + c0;
        float stv = sA[r0 * ASTR_SMALL + 128];
#pragma unroll
        for (int j = 0; j < 8; ++j) acc[j] = fmaf(stv, wsr[j], acc[j]);
    } else {
        layer_acc_s<256, ASTR_BIG>(sA, sW, w0, tid, r0, c0, acc);
    }
    {
#pragma unroll
        for (int j = 0; j < 8; ++j) {
            float v = acc[j] + b0[c0 + j];
            acc[j] = v > 0.f ? v : 0.f;
        }
        *reinterpret_cast<float4*>(sA + r0 * ASTR_SMALL + c0) =
            make_float4(acc[0], acc[1], acc[2], acc[3]);
        *reinterpret_cast<float4*>(sA + r0 * ASTR_SMALL + c0 + 4) =
            make_float4(acc[4], acc[5], acc[6], acc[7]);
    }
    __syncthreads();

#pragma unroll
    for (int j = 0; j < 8; ++j) acc[j] = 0.f;
    layer_acc_s<128, ASTR_SMALL>(sA, sW, w1, tid, r0, c0, acc);
    {
#pragma unroll
        for (int j = 0; j < 8; ++j) {
            float v = acc[j] + b1[c0 + j];
            acc[j] = v > 0.f ? v : 0.f;
        }
        *reinterpret_cast<float4*>(sA + r0 * ASTR_SMALL + c0) =
            make_float4(acc[0], acc[1], acc[2], acc[3]);
        *reinterpret_cast<float4*>(sA + r0 * ASTR_SMALL + c0 + 4) =
            make_float4(acc[4], acc[5], acc[6], acc[7]);
    }
    __syncthreads();

#pragma unroll
    for (int j = 0; j < 8; ++j) acc[j] = 0.f;
    layer_acc_s<128, ASTR_SMALL>(sA, sW, w2, tid, r0, c0, acc);
    {
        int row = row_base + r0;
        if (row < nrows) {
#pragma unroll
            for (int j = 0; j < 8; ++j) acc[j] += b2[c0 + j];

            int node;
            if (MODE == 0)      node = edst[s + row];
            else if (MODE == 1) node = edst[s + half + row];
            else                node = esrc[s + row];

            float* p = x + (size_t)node * Hdim + c0;
            if (MODE == 2) {
                float4 o0 = *reinterpret_cast<const float4*>(p);
                float4 o1 = *reinterpret_cast<const float4*>(p + 4);
                acc[0] += o0.x; acc[1] += o0.y; acc[2] += o0.z; acc[3] += o0.w;
                acc[4] += o1.x; acc[5] += o1.y; acc[6] += o1.z; acc[7] += o1.w;
            }
            *reinterpret_cast<float4*>(p)     = make_float4(acc[0], acc[1], acc[2], acc[3]);
            *reinterpret_cast<float4*>(p + 4) = make_float4(acc[4], acc[5], acc[6], acc[7]);
        }
    }
}

// copy only leaf rows of x (everything else is provably overwritten)
__global__ void leaf_copy_kernel(float* __restrict__ x, const float* __restrict__ x_in)
{
    int idx = blockIdx.x * blockDim.x + threadIdx.x;   // over NL*32 float4s
    if (idx >= NL * 32) return;
    int r = idx >> 5, c4 = idx & 31;
    int b = r >> 13, leaf = r & (NLEAF - 1);
    size_t node = (size_t)b * NPT + leaf;
    reinterpret_cast<float4*>(x + node * Hdim)[c4] =
        reinterpret_cast<const float4*>(x_in + node * Hdim)[c4];
}

template<typename F>
static inline void set_attrs(F f, int smem) {
    cudaFuncSetAttribute(f, cudaFuncAttributeMaxDynamicSharedMemorySize, smem);
    cudaFuncSetAttribute(f, cudaFuncAttributePreferredSharedMemoryCarveout, 100);
}

extern "C" void kernel_launch(void* const* d_in, const int* in_sizes, int n_in,
                              void* d_out, int out_size)
{
    (void)n_in; (void)out_size;

    const float* x_in = (const float*)d_in[0];
    const int*   esrc = (const int*)  d_in[1];
    const int*   edst = (const int*)  d_in[2];
    const float* est  = (const float*)d_in[3];
    const float* ef   = (const float*)d_in[4];

    int wb = (in_sizes[5] == 1) ? 6 : 5;   // input 5 = scalar gcmn_depth

    const float* nem_w0 = (const float*)d_in[wb + 0];
    const float* nem_b0 = (const float*)d_in[wb + 1];
    const float* nem_w1 = (const float*)d_in[wb + 2];
    const float* nem_b1 = (const float*)d_in[wb + 3];
    const float* nem_w2 = (const float*)d_in[wb + 4];
    const float* nem_b2 = (const float*)d_in[wb + 5];
    const float* mg_w0  = (const float*)d_in[wb + 6];
    const float* mg_b0  = (const float*)d_in[wb + 7];
    const float* mg_w1  = (const float*)d_in[wb + 8];
    const float* mg_b1  = (const float*)d_in[wb + 9];
    const float* mg_w2  = (const float*)d_in[wb + 10];
    const float* mg_b2  = (const float*)d_in[wb + 11];
    const float* mr_w0  = (const float*)d_in[wb + 12];
    const float* mr_b0  = (const float*)d_in[wb + 13];
    const float* mr_w1  = (const float*)d_in[wb + 14];
    const float* mr_b1  = (const float*)d_in[wb + 15];
    const float* mr_w2  = (const float*)d_in[wb + 16];
    const float* mr_b2  = (const float*)d_in[wb + 17];

    float* x = (float*)d_out;

    set_attrs(mlp_mma<0>, SMEM_MMA_01);
    set_attrs(mlp_mma<1>, SMEM_MMA_01);
    set_attrs(mlp_mma<2>, SMEM_MMA_2);
    set_attrs(mlp_small<1>, SMEM_SMALL);
    set_attrs(mlp_small<2>, SMEM_SMALL);

    // init: only leaf rows need the original x
    leaf_copy_kernel<<<(NL * 32 + 255) / 256, 256>>>(x, x_in);

    // edge-block layout: block 0 = leaf edges (NL), block d (1..13): 8*(NLEAF>>(d-1)) edges
    int cnt[14], st[14];
    cnt[0] = NL; st[0] = 0;
    for (int d = 1; d < DEPTH; ++d) {
        cnt[d] = 8 * (NLEAF >> (d - 1));
        st[d] = st[d - 1] + cnt[d - 1];
    }

    constexpr int SMALL_THRESH = 2048;

    // ---- nem ----
    mlp_mma<0><<<(NL + 63) / 64, 256, SMEM_MMA_01>>>(
        x, ef, esrc, edst, nullptr,
        nem_w0, nem_b0, nem_w1, nem_b1, nem_w2, nem_b2, 0, 0, NL);

    // ---- mg: upward merge, levels 1..13 ----
    for (int d = 1; d < DEPTH; ++d) {
        int half = cnt[d] / 2;
        if (half <= SMALL_THRESH)
            mlp_small<1><<<(half + 15) / 16, 256, SMEM_SMALL>>>(
                x, nullptr, esrc, edst, nullptr,
                mg_w0, mg_b0, mg_w1, mg_b1, mg_w2, mg_b2, st[d], half, half);
        else
            mlp_mma<1><<<(half + 63) / 64, 256, SMEM_MMA_01>>>(
                x, nullptr, esrc, edst, nullptr,
                mg_w0, mg_b0, mg_w1, mg_b1, mg_w2, mg_b2, st[d], half, half);
    }

    // ---- mr: downward, depth 14..1 ----
    for (int depth = DEPTH; depth >= 1; --depth) {
        int sE, m;
        if (depth == 1) { sE = 0; m = NL; }
        else            { sE = st[depth - 1]; m = cnt[depth - 1]; }
        if (m <= SMALL_THRESH)
            mlp_small<2><<<(m + 15) / 16, 256, SMEM_SMALL>>>(
                x, nullptr, esrc, edst, est,
                mr_w0, mr_b0, mr_w1, mr_b1, mr_w2, mr_b2, sE, 0, m);
        else
            mlp_mma<2><<<(m + 63) / 64, 256, SMEM_MMA_2>>>(
                x, nullptr, esrc, edst, est,
                mr_w0, mr_b0, mr_w1, mr_b1, mr_w2, mr_b2, sE, 0, m);
    }
}

// round 12
// speedup vs baseline: 1.7784x; 1.7784x over previous
#include <cuda_runtime.h>
#include <cstdint>

// Problem constants (shapes fixed by dataset).
constexpr int Hdim   = 128;
constexpr int NLEAF  = 8192;
constexpr int NBATCH = 8;
constexpr int NL     = NBATCH * NLEAF;     // 65536 leaf edges
constexpr int NPT    = 24575;              // nodes per tree
constexpr int NN     = NBATCH * NPT;       // 196600 total nodes
constexpr int DEPTH  = 14;

constexpr int ASTR_BIG   = 260;            // smem stride for 256-wide inputs
constexpr int ASTR_SMALL = 132;            // smem stride for 128/129-wide

// big kernel smem
constexpr int SMEM_BIG_01 = (64 * ASTR_BIG   + 64 * Hdim) * 4;  // 99328
constexpr int SMEM_BIG_2  = (64 * ASTR_SMALL + 64 * Hdim) * 4;  // 66560
// small kernel smem
constexpr int SMEM_SMALL  = (16 * ASTR_BIG   + 64 * Hdim) * 4;  // 49408

// ---------------- packed fp32x2 helpers (Blackwell FFMA2) ----------------
typedef unsigned long long ull;

#define FMA_F32X2(d, a, b, c) \
    asm("fma.rn.f32x2 %0, %1, %2, %3;" : "=l"(d) : "l"(a), "l"(b), "l"(c))

#define PACK_DUP_F32X2(out, x) \
    asm("mov.b64 %0, {%1, %1};" : "=l"(out) : "r"(__float_as_uint(x)))

#define UNPACK_F32X2(lo, hi, v) \
    asm("mov.b64 {%0, %1}, %2;" : "=f"(lo), "=f"(hi) : "l"(v))

// ---- one MLP layer: acc[RPT][4] (f32x2 pairs) += A_tile @ W; 128 threads ----
template<int K, int ASTR, int RPT>
__device__ __forceinline__ void layer_acc2(const float* __restrict__ sA,
                                           float* __restrict__ sW,
                                           const float* __restrict__ w,
                                           int tid, int r0, int c0,
                                           ull (&acc)[RPT][4])
{
#pragma unroll 1
    for (int k0 = 0; k0 < K; k0 += 64) {
        // stage 64x128 weight chunk
        for (int idx = tid; idx < 64 * 32; idx += 128) {
            reinterpret_cast<float4*>(sW)[idx] =
                reinterpret_cast<const float4*>(w + (size_t)k0 * Hdim)[idx];
        }
        __syncthreads();
#pragma unroll 2
        for (int kq = 0; kq < 16; ++kq) {
            float4 av[RPT];
#pragma unroll
            for (int i = 0; i < RPT; ++i)
                av[i] = *reinterpret_cast<const float4*>(sA + (r0 + i) * ASTR + k0 + kq * 4);
#pragma unroll
            for (int t = 0; t < 4; ++t) {
                const float* wr = sW + (kq * 4 + t) * Hdim + c0;
                ulonglong2 wA = *reinterpret_cast<const ulonglong2*>(wr);
                ulonglong2 wB = *reinterpret_cast<const ulonglong2*>(wr + 4);
#pragma unroll
                for (int i = 0; i < RPT; ++i) {
                    float a = reinterpret_cast<const float*>(&av[i])[t];
                    ull aa; PACK_DUP_F32X2(aa, a);
                    FMA_F32X2(acc[i][0], aa, wA.x, acc[i][0]);
                    FMA_F32X2(acc[i][1], aa, wA.y, acc[i][1]);
                    FMA_F32X2(acc[i][2], aa, wB.x, acc[i][2]);
                    FMA_F32X2(acc[i][3], aa, wB.y, acc[i][3]);
                }
            }
        }
        __syncthreads();
    }
}

template<int RPT>
__device__ __forceinline__ void zero_acc2(ull (&acc)[RPT][4]) {
#pragma unroll
    for (int i = 0; i < RPT; ++i)
#pragma unroll
        for (int j = 0; j < 4; ++j) acc[i][j] = 0ull;
}

__device__ __forceinline__ void epi_bias_relu8(ull (&acc)[8][4],
                                               const float* __restrict__ b,
                                               float* __restrict__ sA,
                                               int r0, int c0)
{
    float4 bv0 = *reinterpret_cast<const float4*>(b + c0);
    float4 bv1 = *reinterpret_cast<const float4*>(b + c0 + 4);
    const float bv[8] = {bv0.x, bv0.y, bv0.z, bv0.w, bv1.x, bv1.y, bv1.z, bv1.w};
#pragma unroll
    for (int i = 0; i < 8; ++i) {
        float v[8];
#pragma unroll
        for (int jj = 0; jj < 4; ++jj) {
            float lo, hi; UNPACK_F32X2(lo, hi, acc[i][jj]);
            lo += bv[2 * jj];     hi += bv[2 * jj + 1];
            v[2 * jj]     = lo > 0.f ? lo : 0.f;
            v[2 * jj + 1] = hi > 0.f ? hi : 0.f;
        }
        *reinterpret_cast<float4*>(sA + (r0 + i) * ASTR_SMALL + c0) =
            make_float4(v[0], v[1], v[2], v[3]);
        *reinterpret_cast<float4*>(sA + (r0 + i) * ASTR_SMALL + c0 + 4) =
            make_float4(v[4], v[5], v[6], v[7]);
    }
}

// MODE 0: nem — in=[x[esrc[e]], ef[e]]               (K=256), out -> x[edst[e]]        (set)
// MODE 1: mg  — in=[x[esrc[s+r]], x[esrc[s+half+r]]] (K=256), out -> x[edst[s+half+r]] (set)
// MODE 2: mr  — in=[x[edst[e]], state[e]]            (K=129), out -> x[esrc[e]] += out
template<int MODE>
__global__ void __launch_bounds__(128)
mlp_big(float* __restrict__ x,
        const float* __restrict__ ef,
        const int* __restrict__ esrc,
        const int* __restrict__ edst,
        const float* __restrict__ est,
        const float* __restrict__ w0, const float* __restrict__ b0,
        const float* __restrict__ w1, const float* __restrict__ b1,
        const float* __restrict__ w2, const float* __restrict__ b2,
        int s, int half, int nrows)
{
    constexpr int ASTR0 = (MODE == 2) ? ASTR_SMALL : ASTR_BIG;
    extern __shared__ float sm[];
    float* sA = sm;
    float* sW = sm + 64 * ASTR0;

    const int tid = threadIdx.x;
    const int cx = tid & 15, ry = tid >> 4;      // 16 col-groups x 8 row-groups
    const int c0 = cx * 8, r0 = ry * 8;
    const int row_base = blockIdx.x * 64;

    // ---- gather inputs into sA ----
    if (MODE == 0 || MODE == 1) {
        for (int idx = tid; idx < 64 * 64; idx += 128) {
            int r = idx >> 6, c4 = idx & 63;
            int row = row_base + r;
            if (row < nrows) {
                float4 v;
                if (c4 < 32) {
                    int node = esrc[s + row];
                    v = reinterpret_cast<const float4*>(x + (size_t)node * Hdim)[c4];
                } else if (MODE == 0) {
                    v = reinterpret_cast<const float4*>(ef + (size_t)(s + row) * Hdim)[c4 - 32];
                } else {
                    int node = esrc[s + half + row];
                    v = reinterpret_cast<const float4*>(x + (size_t)node * Hdim)[c4 - 32];
                }
                reinterpret_cast<float4*>(sA + r * ASTR_BIG)[c4] = v;
            }
        }
    } else {
        for (int idx = tid; idx < 64 * 32; idx += 128) {
            int r = idx >> 5, c4 = idx & 31;
            int row = row_base + r;
            if (row < nrows) {
                int node = edst[s + row];
                float4 v = reinterpret_cast<const float4*>(x + (size_t)node * Hdim)[c4];
                reinterpret_cast<float4*>(sA + r * ASTR_SMALL)[c4] = v;
            }
        }
        for (int r = tid; r < 64; r += 128) {
            int row = row_base + r;
            sA[r * ASTR_SMALL + 128] = (row < nrows) ? est[s + row] : 0.f;
        }
    }
    __syncthreads();

    ull acc[8][4];

    // ---- layer 0 ----
    zero_acc2<8>(acc);
    if (MODE == 2) {
        layer_acc2<128, ASTR_SMALL, 8>(sA, sW, w0, tid, r0, c0, acc);
        const float* wsr = w0 + (size_t)128 * Hdim + c0;
        ulonglong2 wsA = *reinterpret_cast<const ulonglong2*>(wsr);
        ulonglong2 wsB = *reinterpret_cast<const ulonglong2*>(wsr + 4);
#pragma unroll
        for (int i = 0; i < 8; ++i) {
            float stv = sA[(r0 + i) * ASTR_SMALL + 128];
            ull aa; PACK_DUP_F32X2(aa, stv);
            FMA_F32X2(acc[i][0], aa, wsA.x, acc[i][0]);
            FMA_F32X2(acc[i][1], aa, wsA.y, acc[i][1]);
            FMA_F32X2(acc[i][2], aa, wsB.x, acc[i][2]);
            FMA_F32X2(acc[i][3], aa, wsB.y, acc[i][3]);
        }
    } else {
        layer_acc2<256, ASTR_BIG, 8>(sA, sW, w0, tid, r0, c0, acc);
    }
    epi_bias_relu8(acc, b0, sA, r0, c0);
    __syncthreads();

    // ---- layer 1 ----
    zero_acc2<8>(acc);
    layer_acc2<128, ASTR_SMALL, 8>(sA, sW, w1, tid, r0, c0, acc);
    epi_bias_relu8(acc, b1, sA, r0, c0);
    __syncthreads();

    // ---- layer 2 + scatter ----
    zero_acc2<8>(acc);
    layer_acc2<128, ASTR_SMALL, 8>(sA, sW, w2, tid, r0, c0, acc);
    {
        float4 bv0 = *reinterpret_cast<const float4*>(b2 + c0);
        float4 bv1 = *reinterpret_cast<const float4*>(b2 + c0 + 4);
        const float bv[8] = {bv0.x, bv0.y, bv0.z, bv0.w, bv1.x, bv1.y, bv1.z, bv1.w};
#pragma unroll
        for (int i = 0; i < 8; ++i) {
            int row = row_base + r0 + i;
            if (row >= nrows) continue;
            float v[8];
#pragma unroll
            for (int jj = 0; jj < 4; ++jj) {
                float lo, hi; UNPACK_F32X2(lo, hi, acc[i][jj]);
                v[2 * jj]     = lo + bv[2 * jj];
                v[2 * jj + 1] = hi + bv[2 * jj + 1];
            }

            int node;
            if (MODE == 0)      node = edst[s + row];
            else if (MODE == 1) node = edst[s + half + row];
            else                node = esrc[s + row];

            float* p = x + (size_t)node * Hdim + c0;
            if (MODE == 2) {
                float4 o0 = *reinterpret_cast<const float4*>(p);
                float4 o1 = *reinterpret_cast<const float4*>(p + 4);
                v[0] += o0.x; v[1] += o0.y; v[2] += o0.z; v[3] += o0.w;
                v[4] += o1.x; v[5] += o1.y; v[6] += o1.z; v[7] += o1.w;
            }
            *reinterpret_cast<float4*>(p)     = make_float4(v[0], v[1], v[2], v[3]);
            *reinterpret_cast<float4*>(p + 4) = make_float4(v[4], v[5], v[6], v[7]);
        }
    }
}

// =============== PAIRED MR kernel: 32 parents -> 64 output rows ============
// For mr depth >= 2: edge rows p and half_m+p share the same parent (edst) and
// differ only in state (0 vs 1). Layer-0 matmul computed ONCE per parent; the
// two activation rows are relu(z+b0) and relu(z+b0+w0_state). Bit-exact vs
// the unpaired path.
__global__ void __launch_bounds__(128)
mlp_big_mr(float* __restrict__ x,
           const int* __restrict__ esrc,
           const int* __restrict__ edst,
           const float* __restrict__ w0, const float* __restrict__ b0,
           const float* __restrict__ w1, const float* __restrict__ b1,
           const float* __restrict__ w2, const float* __restrict__ b2,
           int s, int half_m)
{
    extern __shared__ float sm[];
    float* sA = sm;                              // 64 x ASTR_SMALL
    float* sW = sm + 64 * ASTR_SMALL;

    const int tid = threadIdx.x;
    const int cx = tid & 15, ry = tid >> 4;
    const int c0 = cx * 8;
    const int par_base = blockIdx.x * 32;

    // ---- gather 32 parent rows ----
    for (int idx = tid; idx < 32 * 32; idx += 128) {
        int r = idx >> 5, c4 = idx & 31;
        int p = par_base + r;
        if (p < half_m) {
            int node = edst[s + p];
            float4 v = reinterpret_cast<const float4*>(x + (size_t)node * Hdim)[c4];
            reinterpret_cast<float4*>(sA + r * ASTR_SMALL)[c4] = v;
        }
    }
    __syncthreads();

    // ---- layer 0: 32 rows, RPT=4 ----
    {
        ull acc4[4][4];
        zero_acc2<4>(acc4);
        const int r0p = ry * 4;                  // 8 groups x 4 rows = 32
        layer_acc2<128, ASTR_SMALL, 4>(sA, sW, w0, tid, r0p, c0, acc4);

        float4 bv0 = *reinterpret_cast<const float4*>(b0 + c0);
        float4 bv1 = *reinterpret_cast<const float4*>(b0 + c0 + 4);
        const float bv[8] = {bv0.x, bv0.y, bv0.z, bv0.w, bv1.x, bv1.y, bv1.z, bv1.w};
        const float* wsr = w0 + (size_t)128 * Hdim + c0;
        float4 wsa = *reinterpret_cast<const float4*>(wsr);
        float4 wsb = *reinterpret_cast<const float4*>(wsr + 4);
        const float ws[8] = {wsa.x, wsa.y, wsa.z, wsa.w, wsb.x, wsb.y, wsb.z, wsb.w};

#pragma unroll
        for (int i = 0; i < 4; ++i) {
            int p = r0p + i;                     // local parent row 0..31
            float z[8], l[8], rr[8];
#pragma unroll
            for (int jj = 0; jj < 4; ++jj) {
                float lo, hi; UNPACK_F32X2(lo, hi, acc4[i][jj]);
                z[2 * jj]     = lo + bv[2 * jj];       // state 0: acc + b0
                z[2 * jj + 1] = hi + bv[2 * jj + 1];
            }
#pragma unroll
            for (int j = 0; j < 8; ++j) {
                float lv = z[j];
                float rv = z[j] + ws[j];               // state 1: + w0_state
                l[j]  = lv > 0.f ? lv : 0.f;
                rr[j] = rv > 0.f ? rv : 0.f;
            }
            *reinterpret_cast<float4*>(sA + p * ASTR_SMALL + c0) =
                make_float4(l[0], l[1], l[2], l[3]);
            *reinterpret_cast<float4*>(sA + p * ASTR_SMALL + c0 + 4) =
                make_float4(l[4], l[5], l[6], l[7]);
            *reinterpret_cast<float4*>(sA + (32 + p) * ASTR_SMALL + c0) =
                make_float4(rr[0], rr[1], rr[2], rr[3]);
            *reinterpret_cast<float4*>(sA + (32 + p) * ASTR_SMALL + c0 + 4) =
                make_float4(rr[4], rr[5], rr[6], rr[7]);
        }
    }
    __syncthreads();

    const int r0 = ry * 8;
    ull acc[8][4];

    // ---- layer 1 (64 rows) ----
    zero_acc2<8>(acc);
    layer_acc2<128, ASTR_SMALL, 8>(sA, sW, w1, tid, r0, c0, acc);
    epi_bias_relu8(acc, b1, sA, r0, c0);
    __syncthreads();

    // ---- layer 2 + scatter (64 rows) ----
    zero_acc2<8>(acc);
    layer_acc2<128, ASTR_SMALL, 8>(sA, sW, w2, tid, r0, c0, acc);
    {
        float4 bv0 = *reinterpret_cast<const float4*>(b2 + c0);
        float4 bv1 = *reinterpret_cast<const float4*>(b2 + c0 + 4);
        const float bv[8] = {bv0.x, bv0.y, bv0.z, bv0.w, bv1.x, bv1.y, bv1.z, bv1.w};
#pragma unroll
        for (int i = 0; i < 8; ++i) {
            int li = r0 + i;                     // local row 0..63
            int lp = (li < 32) ? li : (li - 32);
            int p  = par_base + lp;
            if (p >= half_m) continue;
            int erow = (li < 32) ? p : (half_m + p);

            float v[8];
#pragma unroll
            for (int jj = 0; jj < 4; ++jj) {
                float lo, hi; UNPACK_F32X2(lo, hi, acc[i][jj]);
                v[2 * jj]     = lo + bv[2 * jj];
                v[2 * jj + 1] = hi + bv[2 * jj + 1];
            }

            int node = esrc[s + erow];
            float* pp = x + (size_t)node * Hdim + c0;
            float4 o0 = *reinterpret_cast<const float4*>(pp);
            float4 o1 = *reinterpret_cast<const float4*>(pp + 4);
            v[0] += o0.x; v[1] += o0.y; v[2] += o0.z; v[3] += o0.w;
            v[4] += o1.x; v[5] += o1.y; v[6] += o1.z; v[7] += o1.w;
            *reinterpret_cast<float4*>(pp)     = make_float4(v[0], v[1], v[2], v[3]);
            *reinterpret_cast<float4*>(pp + 4) = make_float4(v[4], v[5], v[6], v[7]);
        }
    }
}

// =============== SMALL kernel: 16-row tiles, 256 threads, 1x8/thread =======

template<int K, int ASTR>
__device__ __forceinline__ void layer_acc_s(const float* __restrict__ sA,
                                            float* __restrict__ sW,
                                            const float* __restrict__ w,
                                            int tid, int r0, int c0,
                                            float (&acc)[8])
{
#pragma unroll 1
    for (int k0 = 0; k0 < K; k0 += 64) {
        for (int idx = tid; idx < 64 * 32; idx += 256) {
            reinterpret_cast<float4*>(sW)[idx] =
                reinterpret_cast<const float4*>(w + (size_t)k0 * Hdim)[idx];
        }
        __syncthreads();
#pragma unroll 4
        for (int kq = 0; kq < 16; ++kq) {
            float4 av = *reinterpret_cast<const float4*>(sA + r0 * ASTR + k0 + kq * 4);
#pragma unroll
            for (int t = 0; t < 4; ++t) {
                const float* wr = sW + (kq * 4 + t) * Hdim + c0;
                float4 w0v = *reinterpret_cast<const float4*>(wr);
                float4 w1v = *reinterpret_cast<const float4*>(wr + 4);
                float a = reinterpret_cast<const float*>(&av)[t];
                acc[0] = fmaf(a, w0v.x, acc[0]);
                acc[1] = fmaf(a, w0v.y, acc[1]);
                acc[2] = fmaf(a, w0v.z, acc[2]);
                acc[3] = fmaf(a, w0v.w, acc[3]);
                acc[4] = fmaf(a, w1v.x, acc[4]);
                acc[5] = fmaf(a, w1v.y, acc[5]);
                acc[6] = fmaf(a, w1v.z, acc[6]);
                acc[7] = fmaf(a, w1v.w, acc[7]);
            }
        }
        __syncthreads();
    }
}

template<int MODE>
__global__ void __launch_bounds__(256)
mlp_small(float* __restrict__ x,
          const float* __restrict__ ef,
          const int* __restrict__ esrc,
          const int* __restrict__ edst,
          const float* __restrict__ est,
          const float* __restrict__ w0, const float* __restrict__ b0,
          const float* __restrict__ w1, const float* __restrict__ b1,
          const float* __restrict__ w2, const float* __restrict__ b2,
          int s, int half, int nrows)
{
    extern __shared__ float sm[];
    float* sA = sm;
    float* sW = sm + 16 * ASTR_BIG;

    const int tid = threadIdx.x;
    const int cx = tid & 15, ry = tid >> 4;
    const int c0 = cx * 8, r0 = ry;
    const int row_base = blockIdx.x * 16;

    if (MODE == 0 || MODE == 1) {
        for (int idx = tid; idx < 16 * 64; idx += 256) {
            int r = idx >> 6, c4 = idx & 63;
            int row = row_base + r;
            if (row < nrows) {
                float4 v;
                if (c4 < 32) {
                    int node = esrc[s + row];
                    v = reinterpret_cast<const float4*>(x + (size_t)node * Hdim)[c4];
                } else if (MODE == 0) {
                    v = reinterpret_cast<const float4*>(ef + (size_t)(s + row) * Hdim)[c4 - 32];
                } else {
                    int node = esrc[s + half + row];
                    v = reinterpret_cast<const float4*>(x + (size_t)node * Hdim)[c4 - 32];
                }
                reinterpret_cast<float4*>(sA + r * ASTR_BIG)[c4] = v;
            }
        }
    } else {
        for (int idx = tid; idx < 16 * 32; idx += 256) {
            int r = idx >> 5, c4 = idx & 31;
            int row = row_base + r;
            if (row < nrows) {
                int node = edst[s + row];
                float4 v = reinterpret_cast<const float4*>(x + (size_t)node * Hdim)[c4];
                reinterpret_cast<float4*>(sA + r * ASTR_SMALL)[c4] = v;
            }
        }
        for (int r = tid; r < 16; r += 256) {
            int row = row_base + r;
            sA[r * ASTR_SMALL + 128] = (row < nrows) ? est[s + row] : 0.f;
        }
    }
    __syncthreads();

    float acc[8];

#pragma unroll
    for (int j = 0; j < 8; ++j) acc[j] = 0.f;
    if (MODE == 2) {
        layer_acc_s<128, ASTR_SMALL>(sA, sW, w0, tid, r0, c0, acc);
        const float* wsr = w0 + (size_t)128 * Hdim + c0;
        float stv = sA[r0 * ASTR_SMALL + 128];
#pragma unroll
        for (int j = 0; j < 8; ++j) acc[j] = fmaf(stv, wsr[j], acc[j]);
    } else {
        layer_acc_s<256, ASTR_BIG>(sA, sW, w0, tid, r0, c0, acc);
    }
    {
#pragma unroll
        for (int j = 0; j < 8; ++j) {
            float v = acc[j] + b0[c0 + j];
            acc[j] = v > 0.f ? v : 0.f;
        }
        *reinterpret_cast<float4*>(sA + r0 * ASTR_SMALL + c0) =
            make_float4(acc[0], acc[1], acc[2], acc[3]);
        *reinterpret_cast<float4*>(sA + r0 * ASTR_SMALL + c0 + 4) =
            make_float4(acc[4], acc[5], acc[6], acc[7]);
    }
    __syncthreads();

#pragma unroll
    for (int j = 0; j < 8; ++j) acc[j] = 0.f;
    layer_acc_s<128, ASTR_SMALL>(sA, sW, w1, tid, r0, c0, acc);
    {
#pragma unroll
        for (int j = 0; j < 8; ++j) {
            float v = acc[j] + b1[c0 + j];
            acc[j] = v > 0.f ? v : 0.f;
        }
        *reinterpret_cast<float4*>(sA + r0 * ASTR_SMALL + c0) =
            make_float4(acc[0], acc[1], acc[2], acc[3]);
        *reinterpret_cast<float4*>(sA + r0 * ASTR_SMALL + c0 + 4) =
            make_float4(acc[4], acc[5], acc[6], acc[7]);
    }
    __syncthreads();

#pragma unroll
    for (int j = 0; j < 8; ++j) acc[j] = 0.f;
    layer_acc_s<128, ASTR_SMALL>(sA, sW, w2, tid, r0, c0, acc);
    {
        int row = row_base + r0;
        if (row < nrows) {
#pragma unroll
            for (int j = 0; j < 8; ++j) acc[j] += b2[c0 + j];

            int node;
            if (MODE == 0)      node = edst[s + row];
            else if (MODE == 1) node = edst[s + half + row];
            else                node = esrc[s + row];

            float* p = x + (size_t)node * Hdim + c0;
            if (MODE == 2) {
                float4 o0 = *reinterpret_cast<const float4*>(p);
                float4 o1 = *reinterpret_cast<const float4*>(p + 4);
                acc[0] += o0.x; acc[1] += o0.y; acc[2] += o0.z; acc[3] += o0.w;
                acc[4] += o1.x; acc[5] += o1.y; acc[6] += o1.z; acc[7] += o1.w;
            }
            *reinterpret_cast<float4*>(p)     = make_float4(acc[0], acc[1], acc[2], acc[3]);
            *reinterpret_cast<float4*>(p + 4) = make_float4(acc[4], acc[5], acc[6], acc[7]);
        }
    }
}

// copy only leaf rows of x (everything else is provably overwritten)
__global__ void leaf_copy_kernel(float* __restrict__ x, const float* __restrict__ x_in)
{
    int idx = blockIdx.x * blockDim.x + threadIdx.x;   // over NL*32 float4s
    if (idx >= NL * 32) return;
    int r = idx >> 5, c4 = idx & 31;
    int b = r >> 13, leaf = r & (NLEAF - 1);
    size_t node = (size_t)b * NPT + leaf;
    reinterpret_cast<float4*>(x + node * Hdim)[c4] =
        reinterpret_cast<const float4*>(x_in + node * Hdim)[c4];
}

extern "C" void kernel_launch(void* const* d_in, const int* in_sizes, int n_in,
                              void* d_out, int out_size)
{
    (void)n_in; (void)out_size;

    const float* x_in = (const float*)d_in[0];
    const int*   esrc = (const int*)  d_in[1];
    const int*   edst = (const int*)  d_in[2];
    const float* est  = (const float*)d_in[3];
    const float* ef   = (const float*)d_in[4];

    int wb = (in_sizes[5] == 1) ? 6 : 5;   // input 5 = scalar gcmn_depth

    const float* nem_w0 = (const float*)d_in[wb + 0];
    const float* nem_b0 = (const float*)d_in[wb + 1];
    const float* nem_w1 = (const float*)d_in[wb + 2];
    const float* nem_b1 = (const float*)d_in[wb + 3];
    const float* nem_w2 = (const float*)d_in[wb + 4];
    const float* nem_b2 = (const float*)d_in[wb + 5];
    const float* mg_w0  = (const float*)d_in[wb + 6];
    const float* mg_b0  = (const float*)d_in[wb + 7];
    const float* mg_w1  = (const float*)d_in[wb + 8];
    const float* mg_b1  = (const float*)d_in[wb + 9];
    const float* mg_w2  = (const float*)d_in[wb + 10];
    const float* mg_b2  = (const float*)d_in[wb + 11];
    const float* mr_w0  = (const float*)d_in[wb + 12];
    const float* mr_b0  = (const float*)d_in[wb + 13];
    const float* mr_w1  = (const float*)d_in[wb + 14];
    const float* mr_b1  = (const float*)d_in[wb + 15];
    const float* mr_w2  = (const float*)d_in[wb + 16];
    const float* mr_b2  = (const float*)d_in[wb + 17];

    float* x = (float*)d_out;

    cudaFuncSetAttribute(mlp_big<0>,  cudaFuncAttributeMaxDynamicSharedMemorySize, SMEM_BIG_01);
    cudaFuncSetAttribute(mlp_big<1>,  cudaFuncAttributeMaxDynamicSharedMemorySize, SMEM_BIG_01);
    cudaFuncSetAttribute(mlp_big<2>,  cudaFuncAttributeMaxDynamicSharedMemorySize, SMEM_BIG_2);
    cudaFuncSetAttribute(mlp_big_mr,  cudaFuncAttributeMaxDynamicSharedMemorySize, SMEM_BIG_2);
    cudaFuncSetAttribute(mlp_small<1>, cudaFuncAttributeMaxDynamicSharedMemorySize, SMEM_SMALL);
    cudaFuncSetAttribute(mlp_small<2>, cudaFuncAttributeMaxDynamicSharedMemorySize, SMEM_SMALL);

    // init: only leaf rows need the original x
    leaf_copy_kernel<<<(NL * 32 + 255) / 256, 256>>>(x, x_in);

    // edge-block layout: block 0 = leaf edges (NL), block d (1..13): 8*(NLEAF>>(d-1)) edges
    int cnt[14], st[14];
    cnt[0] = NL; st[0] = 0;
    for (int d = 1; d < DEPTH; ++d) {
        cnt[d] = 8 * (NLEAF >> (d - 1));
        st[d] = st[d - 1] + cnt[d - 1];
    }

    constexpr int SMALL_THRESH = 2048;

    // ---- nem: leaf -> level-1 ----
    mlp_big<0><<<NL / 64, 128, SMEM_BIG_01>>>(
        x, ef, esrc, edst, nullptr,
        nem_w0, nem_b0, nem_w1, nem_b1, nem_w2, nem_b2, 0, 0, NL);

    // ---- mg: upward merge, levels 1..13 (sequential) ----
    for (int d = 1; d < DEPTH; ++d) {
        int half = cnt[d] / 2;
        if (half <= SMALL_THRESH)
            mlp_small<1><<<(half + 15) / 16, 256, SMEM_SMALL>>>(
                x, nullptr, esrc, edst, nullptr,
                mg_w0, mg_b0, mg_w1, mg_b1, mg_w2, mg_b2, st[d], half, half);
        else
            mlp_big<1><<<(half + 63) / 64, 128, SMEM_BIG_01>>>(
                x, nullptr, esrc, edst, nullptr,
                mg_w0, mg_b0, mg_w1, mg_b1, mg_w2, mg_b2, st[d], half, half);
    }

    // ---- mr: downward, depth 14..1 (sequential) ----
    for (int depth = DEPTH; depth >= 1; --depth) {
        if (depth == 1) {
            // leaf edges: unpaired (unique dst, state 0), full 65536 rows
            mlp_big<2><<<(NL + 63) / 64, 128, SMEM_BIG_2>>>(
                x, nullptr, esrc, edst, est,
                mr_w0, mr_b0, mr_w1, mr_b1, mr_w2, mr_b2, 0, 0, NL);
        } else {
            int b = depth - 1;
            int sE = st[b], m = cnt[b];
            if (m <= SMALL_THRESH)
                mlp_small<2><<<(m + 15) / 16, 256, SMEM_SMALL>>>(
                    x, nullptr, esrc, edst, est,
                    mr_w0, mr_b0, mr_w1, mr_b1, mr_w2, mr_b2, sE, 0, m);
            else {
                int half_m = m / 2;
                mlp_big_mr<<<(half_m + 31) / 32, 128, SMEM_BIG_2>>>(
                    x, esrc, edst,
                    mr_w0, mr_b0, mr_w1, mr_b1, mr_w2, mr_b2, sE, half_m);
            }
        }
    }
}